// round 15
// baseline (speedup 1.0000x reference)
#include <cuda_runtime.h>
#include <cstdint>

#define NUM_GRAPHS 1024
#define TPB 128

// Scratch (device globals — no allocations allowed)
__device__ float g_S[NUM_GRAPHS * 3];
__device__ float g_R[NUM_GRAPHS * 3];
__device__ float g_Q[NUM_GRAPHS];
__device__ int   g_done = 0;

// ---------------------------------------------------------------------------
// L2 policy helpers (LDG path — first-class cache_hint support)
// ---------------------------------------------------------------------------
__device__ __forceinline__ uint64_t policy_evict_last() {
    uint64_t p;
    asm("createpolicy.fractional.L2::evict_last.b64 %0, 1.0;" : "=l"(p));
    return p;
}
__device__ __forceinline__ uint64_t policy_evict_first() {
    uint64_t p;
    asm("createpolicy.fractional.L2::evict_first.b64 %0, 1.0;" : "=l"(p));
    return p;
}
__device__ __forceinline__ float4 ldg_pol4(const float4* p, uint64_t pol) {
    float4 v;
    asm("ld.global.nc.L2::cache_hint.v4.f32 {%0,%1,%2,%3}, [%4], %5;"
        : "=f"(v.x), "=f"(v.y), "=f"(v.z), "=f"(v.w)
        : "l"(p), "l"(pol));
    return v;
}

// ---------------------------------------------------------------------------
// Fused kernel, one block of 128 per graph (R5 structure + per-load L2 policy)
// ---------------------------------------------------------------------------
__global__ __launch_bounds__(TPB, 8) void polar_ldgpol_kernel(
    const float* __restrict__ pos,       // [N,3]
    const float* __restrict__ q,         // [N]
    const void*  __restrict__ batch_raw, // [N] int32 or int64, sorted
    float*       __restrict__ out,       // [1024,3]
    int n, float inv_n, int n_pin)
{
    const int tid = threadIdx.x;
    const int g   = blockIdx.x;

    __shared__ int   sh_is64;
    __shared__ int   sh_lo[2], sh_hi[2];
    __shared__ int   sh_last;
    __shared__ float sh[4][7];
    __shared__ float sh_sumq;

    const int* b32 = (const int*)batch_raw;
    const uint64_t polL = policy_evict_last();
    const uint64_t polF = policy_evict_first();

    // --- dtype detect ---
    if (tid < 32) {
        int w = n - 34 + tid;
        int dec = (b32[w + 1] < b32[w]) ? 1 : 0;
        unsigned m = __ballot_sync(0xFFFFFFFFu, dec);
        if (tid == 0) sh_is64 = (m != 0u);
    }
    if (tid == 0) { sh_lo[0] = 0; sh_hi[0] = n; sh_lo[1] = 0; sh_hi[1] = n; }
    __syncthreads();
    const int is64 = sh_is64;

    // --- cooperative 65-ary lower_bound: group0 -> g, group1 -> g+1 ---
    {
        const int grp = tid >> 6;
        const int t   = tid & 63;
        const int target = g + grp;
        #pragma unroll
        for (int r = 0; r < 4; ++r) {
            int lo = sh_lo[grp], hi = sh_hi[grp];
            int size = hi - lo;
            int p = -1, pred = 0;
            if (size > 0) {
                p = lo + (int)(((long long)size * (t + 1)) / 65);
                if (p >= hi) p = hi - 1;
                int v = is64 ? b32[2 * p] : b32[p];
                pred = (v < target);
            }
            __syncthreads();
            if (size > 0) {
                if (pred) atomicMax(&sh_lo[grp], p + 1);
                else      atomicMin(&sh_hi[grp], p);
            }
            __syncthreads();
        }
    }
    const int start = sh_lo[0];
    const int end   = sh_lo[1];

    float sx = 0.f, sy = 0.f, sz = 0.f;
    float rx = 0.f, ry = 0.f, rz = 0.f;
    float qs = 0.f;

    // --- alignment split ---
    int a = (start + 3) & ~3; if (a > end) a = end;
    int b = end & ~3;         if (b < a)   b = a;

    const float3* __restrict__ pos3 = (const float3*)pos;
    for (int i = start + tid; i < a; i += TPB) {
        float  qi = q[i]; float3 p = pos3[i];
        sx = fmaf(qi, p.x, sx); sy = fmaf(qi, p.y, sy); sz = fmaf(qi, p.z, sz);
        rx += p.x; ry += p.y; rz += p.z; qs += qi;
    }
    for (int i = b + tid; i < end; i += TPB) {
        float  qi = q[i]; float3 p = pos3[i];
        sx = fmaf(qi, p.x, sx); sy = fmaf(qi, p.y, sy); sz = fmaf(qi, p.z, sz);
        rx += p.x; ry += p.y; rz += p.z; qs += qi;
    }

    // --- vectorized interior: group gi covers nodes [4gi, 4gi+4) ---
    const float4* __restrict__ pos4 = (const float4*)pos;
    const float4* __restrict__ q4p  = (const float4*)q;
    int gi   = (a >> 2) + tid;
    int gEnd = (b >> 2);
    const int gPin = n_pin >> 2;   // groups below this index are pinned

#define ACC_GROUP(V0, V1, V2, QV)                                            \
    do {                                                                     \
        sx = fmaf((QV).x, (V0).x, sx); sx = fmaf((QV).y, (V0).w, sx);        \
        sx = fmaf((QV).z, (V1).z, sx); sx = fmaf((QV).w, (V2).y, sx);        \
        sy = fmaf((QV).x, (V0).y, sy); sy = fmaf((QV).y, (V1).x, sy);        \
        sy = fmaf((QV).z, (V1).w, sy); sy = fmaf((QV).w, (V2).z, sy);        \
        sz = fmaf((QV).x, (V0).z, sz); sz = fmaf((QV).y, (V1).y, sz);        \
        sz = fmaf((QV).z, (V2).x, sz); sz = fmaf((QV).w, (V2).w, sz);        \
        rx += ((V0).x + (V0).w) + ((V1).z + (V2).y);                         \
        ry += ((V0).y + (V1).x) + ((V1).w + (V2).z);                         \
        rz += ((V0).z + (V1).y) + ((V2).x + (V2).w);                         \
        qs += ((QV).x + (QV).y) + ((QV).z + (QV).w);                         \
    } while (0)

    for (; gi + TPB < gEnd; gi += 2 * TPB) {
        int g2 = gi + TPB;
        uint64_t pol1 = (gi < gPin) ? polL : polF;
        uint64_t pol2 = (g2 < gPin) ? polL : polF;
        float4 a0 = ldg_pol4(&pos4[3 * gi + 0], pol1);
        float4 a1 = ldg_pol4(&pos4[3 * gi + 1], pol1);
        float4 a2 = ldg_pol4(&pos4[3 * gi + 2], pol1);
        float4 qa = ldg_pol4(&q4p[gi], pol1);
        float4 c0 = ldg_pol4(&pos4[3 * g2 + 0], pol2);
        float4 c1 = ldg_pol4(&pos4[3 * g2 + 1], pol2);
        float4 c2 = ldg_pol4(&pos4[3 * g2 + 2], pol2);
        float4 qc = ldg_pol4(&q4p[g2], pol2);
        ACC_GROUP(a0, a1, a2, qa);
        ACC_GROUP(c0, c1, c2, qc);
    }
    for (; gi < gEnd; gi += TPB) {
        uint64_t pol1 = (gi < gPin) ? polL : polF;
        float4 a0 = ldg_pol4(&pos4[3 * gi + 0], pol1);
        float4 a1 = ldg_pol4(&pos4[3 * gi + 1], pol1);
        float4 a2 = ldg_pol4(&pos4[3 * gi + 2], pol1);
        float4 qa = ldg_pol4(&q4p[gi], pol1);
        ACC_GROUP(a0, a1, a2, qa);
    }
#undef ACC_GROUP

    // --- block reduction of 7 floats (4 warps) ---
    const unsigned FULL = 0xFFFFFFFFu;
    #pragma unroll
    for (int off = 16; off > 0; off >>= 1) {
        sx += __shfl_down_sync(FULL, sx, off);
        sy += __shfl_down_sync(FULL, sy, off);
        sz += __shfl_down_sync(FULL, sz, off);
        rx += __shfl_down_sync(FULL, rx, off);
        ry += __shfl_down_sync(FULL, ry, off);
        rz += __shfl_down_sync(FULL, rz, off);
        qs += __shfl_down_sync(FULL, qs, off);
    }
    int wid = tid >> 5, lid = tid & 31;
    if (lid == 0) {
        sh[wid][0] = sx; sh[wid][1] = sy; sh[wid][2] = sz;
        sh[wid][3] = rx; sh[wid][4] = ry; sh[wid][5] = rz;
        sh[wid][6] = qs;
    }
    __syncthreads();
    if (tid == 0) {
        float v0 = 0, v1 = 0, v2 = 0, v3 = 0, v4 = 0, v5 = 0, v6 = 0;
        #pragma unroll
        for (int w = 0; w < TPB / 32; ++w) {
            v0 += sh[w][0]; v1 += sh[w][1]; v2 += sh[w][2];
            v3 += sh[w][3]; v4 += sh[w][4]; v5 += sh[w][5];
            v6 += sh[w][6];
        }
        g_S[3 * g + 0] = v0; g_S[3 * g + 1] = v1; g_S[3 * g + 2] = v2;
        g_R[3 * g + 0] = v3; g_R[3 * g + 1] = v4; g_R[3 * g + 2] = v5;
        g_Q[g] = v6;
        __threadfence();
        int ticket = atomicAdd(&g_done, 1);
        sh_last = (ticket == (int)gridDim.x - 1);
    }
    __syncthreads();

    // --- last block finalizes out = S - mean(q) * R ---
    if (sh_last) {
        __threadfence();
        float s = 0.f;
        for (int k = tid; k < NUM_GRAPHS; k += TPB) s += g_Q[k];
        #pragma unroll
        for (int off = 16; off > 0; off >>= 1)
            s += __shfl_down_sync(FULL, s, off);
        if (lid == 0) sh[wid][0] = s;
        __syncthreads();
        if (tid == 0) {
            float t = 0.f;
            #pragma unroll
            for (int w = 0; w < TPB / 32; ++w) t += sh[w][0];
            sh_sumq = t;
            g_done = 0;
        }
        __syncthreads();
        float mean = sh_sumq * inv_n;
        for (int k = tid; k < NUM_GRAPHS * 3; k += TPB)
            out[k] = fmaf(-mean, g_R[k], g_S[k]);
    }
}

extern "C" void kernel_launch(void* const* d_in, const int* in_sizes, int n_in,
                              void* d_out, int out_size) {
    const float* pos   = (const float*)d_in[0];   // [N,3] float32
    const float* q     = (const float*)d_in[1];   // [N]   float32
    const void*  batch = (const void*)d_in[2];    // [N]   int32/int64 sorted
    float*       out   = (float*)d_out;           // [1024,3] float32
    int n = in_sizes[1];

    int n_pin = (int)(((long long)n * 4) / 5) & ~3;   // pin first 80% (~107 MB)
    polar_ldgpol_kernel<<<NUM_GRAPHS, TPB>>>(pos, q, batch, out, n,
                                             1.0f / (float)n, n_pin);
}